// round 1
// baseline (speedup 1.0000x reference)
#include <cuda_runtime.h>
#include <cstdint>

#define BB 8
#define NN 2048
#define IND 256
#define OUTD 128
#define ROWS (BB * NN)   // 16384
#define NEG_SLOPE 0.2f

// Scratch (device globals — no allocation allowed)
__device__ float g_Wh[ROWS * OUTD];   // 8 MB
__device__ float g_f1[ROWS];
__device__ float g_f2[ROWS];

// ---------------------------------------------------------------------------
// Kernel 1: Wh = h @ W  (16384x256 @ 256x128), epilogue computes
//           f1[r] = Wh[r,:]·a[:128],  f2[r] = Wh[r,:]·a[128:]
// Block: 64 rows x 128 cols (full out width), 256 threads, 8x4 micro-tile.
// ---------------------------------------------------------------------------
__global__ __launch_bounds__(256) void k1_gemm_wh(
    const float* __restrict__ h, const float* __restrict__ W,
    const float* __restrict__ a)
{
    __shared__ float hs[64][32];
    __shared__ float Ws[32][128];

    const int t  = threadIdx.x;
    const int ty = t >> 5;        // warp id 0..7 -> row group
    const int tx = t & 31;        // lane -> col group
    const int row0 = blockIdx.x * 64;

    float acc[8][4];
    #pragma unroll
    for (int i = 0; i < 8; i++)
        #pragma unroll
        for (int j = 0; j < 4; j++) acc[i][j] = 0.f;

    float a1v[4], a2v[4];
    #pragma unroll
    for (int cc = 0; cc < 4; cc++) {
        a1v[cc] = a[tx * 4 + cc];
        a2v[cc] = a[OUTD + tx * 4 + cc];
    }

    const int lr = t >> 3;          // 0..31
    const int lc = (t & 7) * 4;     // 0,4,...,28

    for (int k0 = 0; k0 < IND; k0 += 32) {
        // load h tile (64x32), two row passes
        *(float4*)&hs[lr][lc] =
            *(const float4*)&h[(size_t)(row0 + lr) * IND + k0 + lc];
        *(float4*)&hs[lr + 32][lc] =
            *(const float4*)&h[(size_t)(row0 + lr + 32) * IND + k0 + lc];
        // load W tile (32x128)
        #pragma unroll
        for (int p = 0; p < 4; p++) {
            int idx = t * 4 + p * 1024;      // 0..4095
            int wr = idx >> 7, wc = idx & 127;
            *(float4*)&Ws[wr][wc] = *(const float4*)&W[(size_t)(k0 + wr) * OUTD + wc];
        }
        __syncthreads();

        #pragma unroll 8
        for (int kk = 0; kk < 32; kk++) {
            float4 wq = *(const float4*)&Ws[kk][tx * 4];
            #pragma unroll
            for (int rr = 0; rr < 8; rr++) {
                float hv = hs[ty * 8 + rr][kk];
                acc[rr][0] += hv * wq.x;
                acc[rr][1] += hv * wq.y;
                acc[rr][2] += hv * wq.z;
                acc[rr][3] += hv * wq.w;
            }
        }
        __syncthreads();
    }

    // epilogue: write Wh, reduce f1/f2 across the warp (all lanes share rows)
    #pragma unroll
    for (int rr = 0; rr < 8; rr++) {
        const int r = row0 + ty * 8 + rr;
        float4 o;
        o.x = acc[rr][0]; o.y = acc[rr][1]; o.z = acc[rr][2]; o.w = acc[rr][3];
        *(float4*)&g_Wh[(size_t)r * OUTD + tx * 4] = o;

        float s1 = acc[rr][0] * a1v[0] + acc[rr][1] * a1v[1] +
                   acc[rr][2] * a1v[2] + acc[rr][3] * a1v[3];
        float s2 = acc[rr][0] * a2v[0] + acc[rr][1] * a2v[1] +
                   acc[rr][2] * a2v[2] + acc[rr][3] * a2v[3];
        #pragma unroll
        for (int off = 16; off; off >>= 1) {
            s1 += __shfl_xor_sync(0xFFFFFFFFu, s1, off);
            s2 += __shfl_xor_sync(0xFFFFFFFFu, s2, off);
        }
        if (tx == 0) { g_f1[r] = s1; g_f2[r] = s2; }
    }
}

// ---------------------------------------------------------------------------
// Kernel 2: fused masked-softmax attention aggregate.
// Block = (batch b, 64-row i-tile). Loop j in tiles of 64:
//   w[i][j] = adj[i][j]>0 ? expf(LeakyReLU(f1[b,i]+f2[b,j])) : 0
//   acc[i][o] += w[i][j] * Wh[b][j][o]     (64x128x64 fp32 GEMM per tile)
//   Z[i] += w[i][j]
// out = acc / Z. No max-subtraction needed: |e| = O(10), exp safe in fp32,
// softmax is shift-invariant so this matches the reference exactly.
// ---------------------------------------------------------------------------
#define TJ 64
#define WTS_STRIDE 65
// dynamic smem layout (floats):
//   Whs[64][128]        : 8192
//   wts[64][65]         : 4160
//   fis[64], fjs[64], Zs[64]
#define SM_WHS   0
#define SM_WTS   (64 * 128)
#define SM_FIS   (SM_WTS + 64 * WTS_STRIDE)
#define SM_FJS   (SM_FIS + 64)
#define SM_ZS    (SM_FJS + 64)
#define SM_TOTAL (SM_ZS + 64)
#define SM_BYTES (SM_TOTAL * 4)

__global__ __launch_bounds__(256) void k2_attn(
    const float* __restrict__ adj, float* __restrict__ out)
{
    extern __shared__ float sm[];
    float* Whs = sm + SM_WHS;   // [64][128]
    float* wts = sm + SM_WTS;   // [64][65]
    float* fis = sm + SM_FIS;
    float* fjs = sm + SM_FJS;
    float* Zs  = sm + SM_ZS;

    const int t  = threadIdx.x;
    const int ty = t >> 5;       // warp id -> row group (8 rows each)
    const int tx = t & 31;       // lane -> col group (4 cols each)
    const int b  = blockIdx.y;
    const int i0 = blockIdx.x * 64;

    if (t < 64) {
        fis[t] = g_f1[(size_t)b * NN + i0 + t];
        Zs[t]  = 0.f;
    }

    float acc[8][4];
    #pragma unroll
    for (int i = 0; i < 8; i++)
        #pragma unroll
        for (int j = 0; j < 4; j++) acc[i][j] = 0.f;

    // w-compute mapping: thread handles one row (t>>2), 16 consecutive j
    const int wr  = t >> 2;          // 0..63
    const int wc0 = (t & 3) * 16;
    float Zpart = 0.f;

    __syncthreads();
    const float fi_w = fis[wr];
    const float* Whb = g_Wh + (size_t)b * NN * OUTD;
    const float* f2b = g_f2 + (size_t)b * NN;

    for (int j0 = 0; j0 < NN; j0 += TJ) {
        // load Wh tile (64x128 floats), 8 float4 per thread, linear mapping
        #pragma unroll
        for (int p = 0; p < 8; p++) {
            int idx = (t + p * 256) * 4;        // 0..8191
            int r = idx >> 7, c = idx & 127;
            *(float4*)&Whs[r * 128 + c] =
                *(const float4*)&Whb[(size_t)(j0 + r) * OUTD + c];
        }
        if (t < 64) fjs[t] = f2b[j0 + t];
        __syncthreads();

        // weight tile: 16 entries per thread, vectorized adj loads
        {
            const float* adjrow = adj + (size_t)(i0 + wr) * NN + j0 + wc0;
            #pragma unroll
            for (int q = 0; q < 4; q++) {
                float4 av = *(const float4*)&adjrow[q * 4];
                float am[4] = {av.x, av.y, av.z, av.w};
                #pragma unroll
                for (int s = 0; s < 4; s++) {
                    int jj = wc0 + q * 4 + s;
                    float e = fi_w + fjs[jj];
                    e = (e >= 0.f) ? e : NEG_SLOPE * e;
                    float w = (am[s] > 0.f) ? __expf(e) : 0.f;
                    wts[wr * WTS_STRIDE + jj] = w;
                    Zpart += w;
                }
            }
        }
        __syncthreads();

        // GEMM accumulate: acc[8][4] += w[row][jj] * Whs[jj][col]
        #pragma unroll 8
        for (int jj = 0; jj < TJ; jj++) {
            float4 wq = *(const float4*)&Whs[jj * 128 + tx * 4];
            #pragma unroll
            for (int rr = 0; rr < 8; rr++) {
                float wv = wts[(ty * 8 + rr) * WTS_STRIDE + jj];
                acc[rr][0] += wv * wq.x;
                acc[rr][1] += wv * wq.y;
                acc[rr][2] += wv * wq.z;
                acc[rr][3] += wv * wq.w;
            }
        }
        __syncthreads();
    }

    atomicAdd(&Zs[wr], Zpart);
    __syncthreads();

    #pragma unroll
    for (int rr = 0; rr < 8; rr++) {
        const int r = ty * 8 + rr;
        const float inv = 1.f / Zs[r];
        float4 o;
        o.x = acc[rr][0] * inv; o.y = acc[rr][1] * inv;
        o.z = acc[rr][2] * inv; o.w = acc[rr][3] * inv;
        *(float4*)&out[((size_t)b * NN + i0 + r) * OUTD + tx * 4] = o;
    }
}

// ---------------------------------------------------------------------------
extern "C" void kernel_launch(void* const* d_in, const int* in_sizes, int n_in,
                              void* d_out, int out_size)
{
    const float* h   = (const float*)d_in[0];   // (8, 2048, 256)
    const float* adj = (const float*)d_in[1];   // (2048, 2048)
    const float* W   = (const float*)d_in[2];   // (256, 128)
    const float* a   = (const float*)d_in[3];   // (256,)
    float* out = (float*)d_out;                 // (8, 2048, 128)

    k1_gemm_wh<<<ROWS / 64, 256>>>(h, W, a);

    cudaFuncSetAttribute(k2_attn, cudaFuncAttributeMaxDynamicSharedMemorySize,
                         SM_BYTES);
    k2_attn<<<dim3(NN / 64, BB), 256, SM_BYTES>>>(adj, out);
}

// round 2
// speedup vs baseline: 1.8412x; 1.8412x over previous
#include <cuda_runtime.h>
#include <cstdint>

#define BB 8
#define NN 2048
#define IND 256
#define OUTD 128
#define ROWS (BB * NN)   // 16384
#define NEG_SLOPE 0.2f

// Scratch (device globals — no allocation allowed)
__device__ float g_Wh[ROWS * OUTD];   // 8 MB
__device__ float g_f1[ROWS];
__device__ float g_f2[ROWS];

// ---------------------------------------------------------------------------
// Kernel 1: Wh = h @ W  (16384x256 @ 256x128), epilogue computes
//           f1[r] = Wh[r,:]·a[:128],  f2[r] = Wh[r,:]·a[128:]
// ---------------------------------------------------------------------------
__global__ __launch_bounds__(256) void k1_gemm_wh(
    const float* __restrict__ h, const float* __restrict__ W,
    const float* __restrict__ a)
{
    __shared__ float hs[64][32];
    __shared__ float Ws[32][128];

    const int t  = threadIdx.x;
    const int ty = t >> 5;
    const int tx = t & 31;
    const int row0 = blockIdx.x * 64;

    float acc[8][4];
    #pragma unroll
    for (int i = 0; i < 8; i++)
        #pragma unroll
        for (int j = 0; j < 4; j++) acc[i][j] = 0.f;

    float a1v[4], a2v[4];
    #pragma unroll
    for (int cc = 0; cc < 4; cc++) {
        a1v[cc] = a[tx * 4 + cc];
        a2v[cc] = a[OUTD + tx * 4 + cc];
    }

    const int lr = t >> 3;
    const int lc = (t & 7) * 4;

    for (int k0 = 0; k0 < IND; k0 += 32) {
        *(float4*)&hs[lr][lc] =
            *(const float4*)&h[(size_t)(row0 + lr) * IND + k0 + lc];
        *(float4*)&hs[lr + 32][lc] =
            *(const float4*)&h[(size_t)(row0 + lr + 32) * IND + k0 + lc];
        #pragma unroll
        for (int p = 0; p < 4; p++) {
            int idx = t * 4 + p * 1024;
            int wr = idx >> 7, wc = idx & 127;
            *(float4*)&Ws[wr][wc] = *(const float4*)&W[(size_t)(k0 + wr) * OUTD + wc];
        }
        __syncthreads();

        #pragma unroll 8
        for (int kk = 0; kk < 32; kk++) {
            float4 wq = *(const float4*)&Ws[kk][tx * 4];
            #pragma unroll
            for (int rr = 0; rr < 8; rr++) {
                float hv = hs[ty * 8 + rr][kk];
                acc[rr][0] += hv * wq.x;
                acc[rr][1] += hv * wq.y;
                acc[rr][2] += hv * wq.z;
                acc[rr][3] += hv * wq.w;
            }
        }
        __syncthreads();
    }

    #pragma unroll
    for (int rr = 0; rr < 8; rr++) {
        const int r = row0 + ty * 8 + rr;
        float4 o;
        o.x = acc[rr][0]; o.y = acc[rr][1]; o.z = acc[rr][2]; o.w = acc[rr][3];
        *(float4*)&g_Wh[(size_t)r * OUTD + tx * 4] = o;

        float s1 = acc[rr][0] * a1v[0] + acc[rr][1] * a1v[1] +
                   acc[rr][2] * a1v[2] + acc[rr][3] * a1v[3];
        float s2 = acc[rr][0] * a2v[0] + acc[rr][1] * a2v[1] +
                   acc[rr][2] * a2v[2] + acc[rr][3] * a2v[3];
        #pragma unroll
        for (int off = 16; off; off >>= 1) {
            s1 += __shfl_xor_sync(0xFFFFFFFFu, s1, off);
            s2 += __shfl_xor_sync(0xFFFFFFFFu, s2, off);
        }
        if (tx == 0) { g_f1[r] = s1; g_f2[r] = s2; }
    }
}

// ---------------------------------------------------------------------------
// Kernel 2: fused masked-softmax attention aggregate, tf32 tensor cores.
// Block = (b, 64-row i-tile), 256 threads = 8 warps (4 on M x 2 on N).
// Per 64-wide j-tile:
//   Whs[64][136] <- tf32(Wh[j0:j0+64][:])     (stride 136 -> conflict-free B)
//   wts[64][68]  <- tf32(adj>0 ? exp(leaky(fi+fj)) : 0), Z += tf32 weight
//   mma.m16n8k8.tf32: acc[64x128] += wts @ Whs
// Z accumulates the tf32-ROUNDED weights so softmax stays exactly normalized.
// ---------------------------------------------------------------------------
#define WHS_STRIDE 136
#define WTS_STRIDE 68
#define SM_WHS  0
#define SM_WTS  (64 * WHS_STRIDE)
#define SM_FJS  (SM_WTS + 64 * WTS_STRIDE)
#define SM_ZS   (SM_FJS + 64)
#define SM_TOT  (SM_ZS + 64)
#define SM_BYTES (SM_TOT * 4)

__device__ __forceinline__ uint32_t f2tf32(float x) {
    uint32_t r;
    asm("cvt.rna.tf32.f32 %0, %1;" : "=r"(r) : "f"(x));
    return r;
}

__device__ __forceinline__ void mma_tf32(float* d, const uint32_t* a,
                                         uint32_t b0, uint32_t b1) {
    asm volatile(
        "mma.sync.aligned.m16n8k8.row.col.f32.tf32.tf32.f32 "
        "{%0,%1,%2,%3}, {%4,%5,%6,%7}, {%8,%9}, {%0,%1,%2,%3};\n"
        : "+f"(d[0]), "+f"(d[1]), "+f"(d[2]), "+f"(d[3])
        : "r"(a[0]), "r"(a[1]), "r"(a[2]), "r"(a[3]), "r"(b0), "r"(b1));
}

__global__ __launch_bounds__(256, 2) void k2_attn(
    const float* __restrict__ adj, float* __restrict__ out)
{
    extern __shared__ float sm[];
    float*    Whs  = sm + SM_WHS;                 // [64][136] tf32 bits
    float*    wts  = sm + SM_WTS;                 // [64][68]  tf32 bits
    float*    fjs  = sm + SM_FJS;
    float*    Zs   = sm + SM_ZS;
    const uint32_t* Whsu = (const uint32_t*)Whs;
    const uint32_t* wtsu = (const uint32_t*)wts;

    const int t    = threadIdx.x;
    const int wid  = t >> 5;
    const int lane = t & 31;
    const int gid  = lane >> 2;      // mma groupID
    const int tig  = lane & 3;       // mma threadID-in-group
    const int b    = blockIdx.y;
    const int i0   = blockIdx.x * 64;

    const int m_warp = (wid & 3) * 16;
    const int n_warp = (wid >> 2) * 64;

    // weight-compute mapping: one row per 4 threads, 16 cols each
    const int wr  = t >> 2;          // 0..63
    const int wc0 = (t & 3) * 16;

    if (t < 64) Zs[t] = 0.f;

    const float fi_w = g_f1[(size_t)b * NN + i0 + wr];
    const float* Whb = g_Wh + (size_t)b * NN * OUTD;
    const float* f2b = g_f2 + (size_t)b * NN;

    float acc[8][4];
    #pragma unroll
    for (int i = 0; i < 8; i++)
        #pragma unroll
        for (int j = 0; j < 4; j++) acc[i][j] = 0.f;

    float Zpart = 0.f;

    for (int j0 = 0; j0 < NN; j0 += 64) {
        // ---- load Wh tile (64x128) -> Whs (tf32-rounded), 8 float4/thread
        #pragma unroll
        for (int p = 0; p < 8; p++) {
            int idx = t + p * 256;            // float4 index, 0..2047
            int r = idx >> 5, c4 = (idx & 31) * 4;
            float4 v = *(const float4*)&Whb[(size_t)(j0 + r) * OUTD + c4];
            uint32_t* dst = (uint32_t*)&Whs[r * WHS_STRIDE + c4];
            dst[0] = f2tf32(v.x); dst[1] = f2tf32(v.y);
            dst[2] = f2tf32(v.z); dst[3] = f2tf32(v.w);
        }
        if (t < 64) fjs[t] = f2b[j0 + t];
        __syncthreads();

        // ---- weight tile: 16 entries/thread, tf32-rounded, Z on rounded vals
        {
            const float* adjrow = adj + (size_t)(i0 + wr) * NN + j0 + wc0;
            #pragma unroll
            for (int q = 0; q < 4; q++) {
                float4 av = *(const float4*)&adjrow[q * 4];
                float am[4] = {av.x, av.y, av.z, av.w};
                uint32_t wb[4];
                #pragma unroll
                for (int s = 0; s < 4; s++) {
                    int jj = wc0 + q * 4 + s;
                    float e = fi_w + fjs[jj];
                    e = (e >= 0.f) ? e : NEG_SLOPE * e;
                    float w = (am[s] > 0.f) ? __expf(e) : 0.f;
                    uint32_t wt = f2tf32(w);
                    wb[s] = wt;
                    Zpart += __uint_as_float(wt);
                }
                *(uint4*)&wts[wr * WTS_STRIDE + wc0 + q * 4] =
                    make_uint4(wb[0], wb[1], wb[2], wb[3]);
            }
        }
        __syncthreads();

        // ---- tensor-core accumulate: acc += wts(64x64) @ Whs(64x128)
        #pragma unroll
        for (int k0 = 0; k0 < 64; k0 += 8) {
            uint32_t afrag[4];
            {
                int base = (m_warp + gid) * WTS_STRIDE + k0 + tig;
                afrag[0] = wtsu[base];
                afrag[1] = wtsu[base + 8 * WTS_STRIDE];
                afrag[2] = wtsu[base + 4];
                afrag[3] = wtsu[base + 8 * WTS_STRIDE + 4];
            }
            #pragma unroll
            for (int nt = 0; nt < 8; nt++) {
                int nb = n_warp + nt * 8 + gid;
                uint32_t b0 = Whsu[(k0 + tig) * WHS_STRIDE + nb];
                uint32_t b1 = Whsu[(k0 + tig + 4) * WHS_STRIDE + nb];
                mma_tf32(acc[nt], afrag, b0, b1);
            }
        }
        __syncthreads();
    }

    atomicAdd(&Zs[wr], Zpart);
    __syncthreads();

    // ---- epilogue: divide by Z, store
    {
        const int row0e = m_warp + gid;
        const int row1e = row0e + 8;
        const float inv0 = 1.f / Zs[row0e];
        const float inv1 = 1.f / Zs[row1e];
        float* out0 = out + ((size_t)b * NN + i0 + row0e) * OUTD;
        float* out1 = out + ((size_t)b * NN + i0 + row1e) * OUTD;
        #pragma unroll
        for (int nt = 0; nt < 8; nt++) {
            int col = n_warp + nt * 8 + tig * 2;
            *(float2*)&out0[col] = make_float2(acc[nt][0] * inv0,
                                               acc[nt][1] * inv0);
            *(float2*)&out1[col] = make_float2(acc[nt][2] * inv1,
                                               acc[nt][3] * inv1);
        }
    }
}

// ---------------------------------------------------------------------------
extern "C" void kernel_launch(void* const* d_in, const int* in_sizes, int n_in,
                              void* d_out, int out_size)
{
    const float* h   = (const float*)d_in[0];   // (8, 2048, 256)
    const float* adj = (const float*)d_in[1];   // (2048, 2048)
    const float* W   = (const float*)d_in[2];   // (256, 128)
    const float* a   = (const float*)d_in[3];   // (256,)
    float* out = (float*)d_out;                 // (8, 2048, 128)

    k1_gemm_wh<<<ROWS / 64, 256>>>(h, W, a);

    cudaFuncSetAttribute(k2_attn, cudaFuncAttributeMaxDynamicSharedMemorySize,
                         SM_BYTES);
    k2_attn<<<dim3(NN / 64, BB), 256, SM_BYTES>>>(adj, out);
}

// round 3
// speedup vs baseline: 1.8632x; 1.0119x over previous
#include <cuda_runtime.h>
#include <cstdint>

#define BB 8
#define NN 2048
#define IND 256
#define OUTD 128
#define ROWS (BB * NN)   // 16384
#define NEG_SLOPE 0.2f

// Scratch (device globals — no allocation allowed)
__device__ float g_Wh[ROWS * OUTD];   // 8 MB
__device__ float g_f1[ROWS];
__device__ float g_f2[ROWS];

// ---------------------------------------------------------------------------
// Kernel 1: Wh = h @ W  (16384x256 @ 256x128), epilogue computes
//           f1[r] = Wh[r,:]·a[:128],  f2[r] = Wh[r,:]·a[128:]
// ---------------------------------------------------------------------------
__global__ __launch_bounds__(256) void k1_gemm_wh(
    const float* __restrict__ h, const float* __restrict__ W,
    const float* __restrict__ a)
{
    __shared__ float hs[64][32];
    __shared__ float Ws[32][128];

    const int t  = threadIdx.x;
    const int ty = t >> 5;
    const int tx = t & 31;
    const int row0 = blockIdx.x * 64;

    float acc[8][4];
    #pragma unroll
    for (int i = 0; i < 8; i++)
        #pragma unroll
        for (int j = 0; j < 4; j++) acc[i][j] = 0.f;

    float a1v[4], a2v[4];
    #pragma unroll
    for (int cc = 0; cc < 4; cc++) {
        a1v[cc] = a[tx * 4 + cc];
        a2v[cc] = a[OUTD + tx * 4 + cc];
    }

    const int lr = t >> 3;
    const int lc = (t & 7) * 4;

    for (int k0 = 0; k0 < IND; k0 += 32) {
        *(float4*)&hs[lr][lc] =
            *(const float4*)&h[(size_t)(row0 + lr) * IND + k0 + lc];
        *(float4*)&hs[lr + 32][lc] =
            *(const float4*)&h[(size_t)(row0 + lr + 32) * IND + k0 + lc];
        #pragma unroll
        for (int p = 0; p < 4; p++) {
            int idx = t * 4 + p * 1024;
            int wr = idx >> 7, wc = idx & 127;
            *(float4*)&Ws[wr][wc] = *(const float4*)&W[(size_t)(k0 + wr) * OUTD + wc];
        }
        __syncthreads();

        #pragma unroll 8
        for (int kk = 0; kk < 32; kk++) {
            float4 wq = *(const float4*)&Ws[kk][tx * 4];
            #pragma unroll
            for (int rr = 0; rr < 8; rr++) {
                float hv = hs[ty * 8 + rr][kk];
                acc[rr][0] += hv * wq.x;
                acc[rr][1] += hv * wq.y;
                acc[rr][2] += hv * wq.z;
                acc[rr][3] += hv * wq.w;
            }
        }
        __syncthreads();
    }

    #pragma unroll
    for (int rr = 0; rr < 8; rr++) {
        const int r = row0 + ty * 8 + rr;
        float4 o;
        o.x = acc[rr][0]; o.y = acc[rr][1]; o.z = acc[rr][2]; o.w = acc[rr][3];
        *(float4*)&g_Wh[(size_t)r * OUTD + tx * 4] = o;

        float s1 = acc[rr][0] * a1v[0] + acc[rr][1] * a1v[1] +
                   acc[rr][2] * a1v[2] + acc[rr][3] * a1v[3];
        float s2 = acc[rr][0] * a2v[0] + acc[rr][1] * a2v[1] +
                   acc[rr][2] * a2v[2] + acc[rr][3] * a2v[3];
        #pragma unroll
        for (int off = 16; off; off >>= 1) {
            s1 += __shfl_xor_sync(0xFFFFFFFFu, s1, off);
            s2 += __shfl_xor_sync(0xFFFFFFFFu, s2, off);
        }
        if (tx == 0) { g_f1[r] = s1; g_f2[r] = s2; }
    }
}

// ---------------------------------------------------------------------------
// Kernel 2: fused masked-softmax attention aggregate, tf32 tensor cores.
// Block = (b, 64-row i-tile), 256 threads = 8 warps (4 on M x 2 on N).
// Per 64-wide j-tile:
//   Whs[64][136] <- tf32(Wh[j0:j0+64][:])     (stride 136 -> conflict-free B)
//   wts[64][68]  <- tf32(adj>0 ? exp(leaky(fi+fj)) : 0), Z += tf32 weight
//   mma.m16n8k8.tf32: acc[64x128] += wts @ Whs
// Z accumulates the tf32-ROUNDED weights so softmax stays exactly normalized.
// ---------------------------------------------------------------------------
#define WHS_STRIDE 136
#define WTS_STRIDE 68
#define SM_WHS  0
#define SM_WTS  (64 * WHS_STRIDE)
#define SM_FJS  (SM_WTS + 64 * WTS_STRIDE)
#define SM_ZS   (SM_FJS + 64)
#define SM_TOT  (SM_ZS + 64)
#define SM_BYTES (SM_TOT * 4)

__device__ __forceinline__ uint32_t f2tf32(float x) {
    uint32_t r;
    asm("cvt.rna.tf32.f32 %0, %1;" : "=r"(r) : "f"(x));
    return r;
}

__device__ __forceinline__ void mma_tf32(float* d, const uint32_t* a,
                                         uint32_t b0, uint32_t b1) {
    asm volatile(
        "mma.sync.aligned.m16n8k8.row.col.f32.tf32.tf32.f32 "
        "{%0,%1,%2,%3}, {%4,%5,%6,%7}, {%8,%9}, {%0,%1,%2,%3};\n"
        : "+f"(d[0]), "+f"(d[1]), "+f"(d[2]), "+f"(d[3])
        : "r"(a[0]), "r"(a[1]), "r"(a[2]), "r"(a[3]), "r"(b0), "r"(b1));
}

__global__ __launch_bounds__(256, 2) void k2_attn(
    const float* __restrict__ adj, float* __restrict__ out)
{
    extern __shared__ float sm[];
    float*    Whs  = sm + SM_WHS;                 // [64][136] tf32 bits
    float*    wts  = sm + SM_WTS;                 // [64][68]  tf32 bits
    float*    fjs  = sm + SM_FJS;
    float*    Zs   = sm + SM_ZS;
    const uint32_t* Whsu = (const uint32_t*)Whs;
    const uint32_t* wtsu = (const uint32_t*)wts;

    const int t    = threadIdx.x;
    const int wid  = t >> 5;
    const int lane = t & 31;
    const int gid  = lane >> 2;      // mma groupID
    const int tig  = lane & 3;       // mma threadID-in-group
    const int b    = blockIdx.y;
    const int i0   = blockIdx.x * 64;

    const int m_warp = (wid & 3) * 16;
    const int n_warp = (wid >> 2) * 64;

    // weight-compute mapping: one row per 4 threads, 16 cols each
    const int wr  = t >> 2;          // 0..63
    const int wc0 = (t & 3) * 16;

    if (t < 64) Zs[t] = 0.f;

    const float fi_w = g_f1[(size_t)b * NN + i0 + wr];
    const float* Whb = g_Wh + (size_t)b * NN * OUTD;
    const float* f2b = g_f2 + (size_t)b * NN;

    float acc[8][4];
    #pragma unroll
    for (int i = 0; i < 8; i++)
        #pragma unroll
        for (int j = 0; j < 4; j++) acc[i][j] = 0.f;

    float Zpart = 0.f;

    for (int j0 = 0; j0 < NN; j0 += 64) {
        // ---- load Wh tile (64x128) -> Whs (tf32-rounded), 8 float4/thread
        #pragma unroll
        for (int p = 0; p < 8; p++) {
            int idx = t + p * 256;            // float4 index, 0..2047
            int r = idx >> 5, c4 = (idx & 31) * 4;
            float4 v = *(const float4*)&Whb[(size_t)(j0 + r) * OUTD + c4];
            uint32_t* dst = (uint32_t*)&Whs[r * WHS_STRIDE + c4];
            dst[0] = f2tf32(v.x); dst[1] = f2tf32(v.y);
            dst[2] = f2tf32(v.z); dst[3] = f2tf32(v.w);
        }
        if (t < 64) fjs[t] = f2b[j0 + t];
        __syncthreads();

        // ---- weight tile: 16 entries/thread, tf32-rounded, Z on rounded vals
        {
            const float* adjrow = adj + (size_t)(i0 + wr) * NN + j0 + wc0;
            #pragma unroll
            for (int q = 0; q < 4; q++) {
                float4 av = *(const float4*)&adjrow[q * 4];
                float am[4] = {av.x, av.y, av.z, av.w};
                uint32_t wb[4];
                #pragma unroll
                for (int s = 0; s < 4; s++) {
                    int jj = wc0 + q * 4 + s;
                    float e = fi_w + fjs[jj];
                    e = (e >= 0.f) ? e : NEG_SLOPE * e;
                    float w = (am[s] > 0.f) ? __expf(e) : 0.f;
                    uint32_t wt = f2tf32(w);
                    wb[s] = wt;
                    Zpart += __uint_as_float(wt);
                }
                *(uint4*)&wts[wr * WTS_STRIDE + wc0 + q * 4] =
                    make_uint4(wb[0], wb[1], wb[2], wb[3]);
            }
        }
        __syncthreads();

        // ---- tensor-core accumulate: acc += wts(64x64) @ Whs(64x128)
        #pragma unroll
        for (int k0 = 0; k0 < 64; k0 += 8) {
            uint32_t afrag[4];
            {
                int base = (m_warp + gid) * WTS_STRIDE + k0 + tig;
                afrag[0] = wtsu[base];
                afrag[1] = wtsu[base + 8 * WTS_STRIDE];
                afrag[2] = wtsu[base + 4];
                afrag[3] = wtsu[base + 8 * WTS_STRIDE + 4];
            }
            #pragma unroll
            for (int nt = 0; nt < 8; nt++) {
                int nb = n_warp + nt * 8 + gid;
                uint32_t b0 = Whsu[(k0 + tig) * WHS_STRIDE + nb];
                uint32_t b1 = Whsu[(k0 + tig + 4) * WHS_STRIDE + nb];
                mma_tf32(acc[nt], afrag, b0, b1);
            }
        }
        __syncthreads();
    }

    atomicAdd(&Zs[wr], Zpart);
    __syncthreads();

    // ---- epilogue: divide by Z, store
    {
        const int row0e = m_warp + gid;
        const int row1e = row0e + 8;
        const float inv0 = 1.f / Zs[row0e];
        const float inv1 = 1.f / Zs[row1e];
        float* out0 = out + ((size_t)b * NN + i0 + row0e) * OUTD;
        float* out1 = out + ((size_t)b * NN + i0 + row1e) * OUTD;
        #pragma unroll
        for (int nt = 0; nt < 8; nt++) {
            int col = n_warp + nt * 8 + tig * 2;
            *(float2*)&out0[col] = make_float2(acc[nt][0] * inv0,
                                               acc[nt][1] * inv0);
            *(float2*)&out1[col] = make_float2(acc[nt][2] * inv1,
                                               acc[nt][3] * inv1);
        }
    }
}

// ---------------------------------------------------------------------------
extern "C" void kernel_launch(void* const* d_in, const int* in_sizes, int n_in,
                              void* d_out, int out_size)
{
    const float* h   = (const float*)d_in[0];   // (8, 2048, 256)
    const float* adj = (const float*)d_in[1];   // (2048, 2048)
    const float* W   = (const float*)d_in[2];   // (256, 128)
    const float* a   = (const float*)d_in[3];   // (256,)
    float* out = (float*)d_out;                 // (8, 2048, 128)

    k1_gemm_wh<<<ROWS / 64, 256>>>(h, W, a);

    cudaFuncSetAttribute(k2_attn, cudaFuncAttributeMaxDynamicSharedMemorySize,
                         SM_BYTES);
    k2_attn<<<dim3(NN / 64, BB), 256, SM_BYTES>>>(adj, out);
}

// round 4
// speedup vs baseline: 2.0805x; 1.1166x over previous
#include <cuda_runtime.h>
#include <cstdint>

#define BB 8
#define NN 2048
#define IND 256
#define OUTD 128
#define ROWS (BB * NN)   // 16384
#define NEG_SLOPE 0.2f

// Scratch (device globals — no allocation allowed)
__device__ float g_Wh[ROWS * OUTD];   // 8 MB, tf32-rounded values
__device__ float g_f1[ROWS];
__device__ float g_f2[ROWS];

__device__ __forceinline__ uint32_t f2tf32(float x) {
    uint32_t r;
    asm("cvt.rna.tf32.f32 %0, %1;" : "=r"(r) : "f"(x));
    return r;
}

__device__ __forceinline__ void cp_async16(void* dst_smem, const void* src) {
    uint32_t d = (uint32_t)__cvta_generic_to_shared(dst_smem);
    asm volatile("cp.async.cg.shared.global [%0], [%1], 16;\n"
                 :: "r"(d), "l"(src));
}
#define CP_COMMIT() asm volatile("cp.async.commit_group;\n" ::: "memory")
#define CP_WAIT0()  asm volatile("cp.async.wait_group 0;\n" ::: "memory")

// ---------------------------------------------------------------------------
// Kernel 1: Wh = h @ W  (16384x256 @ 256x128), epilogue computes
//   f1[r] = Wh[r,:]·a[:128],  f2[r] = Wh[r,:]·a[128:]   (full precision)
// and stores Wh tf32-ROUNDED so k2's MMA B operand needs no conversion.
// ---------------------------------------------------------------------------
__global__ __launch_bounds__(256) void k1_gemm_wh(
    const float* __restrict__ h, const float* __restrict__ W,
    const float* __restrict__ a)
{
    __shared__ float hs[64][32];
    __shared__ float Ws[32][128];

    const int t  = threadIdx.x;
    const int ty = t >> 5;
    const int tx = t & 31;
    const int row0 = blockIdx.x * 64;

    float acc[8][4];
    #pragma unroll
    for (int i = 0; i < 8; i++)
        #pragma unroll
        for (int j = 0; j < 4; j++) acc[i][j] = 0.f;

    float a1v[4], a2v[4];
    #pragma unroll
    for (int cc = 0; cc < 4; cc++) {
        a1v[cc] = a[tx * 4 + cc];
        a2v[cc] = a[OUTD + tx * 4 + cc];
    }

    const int lr = t >> 3;
    const int lc = (t & 7) * 4;

    for (int k0 = 0; k0 < IND; k0 += 32) {
        *(float4*)&hs[lr][lc] =
            *(const float4*)&h[(size_t)(row0 + lr) * IND + k0 + lc];
        *(float4*)&hs[lr + 32][lc] =
            *(const float4*)&h[(size_t)(row0 + lr + 32) * IND + k0 + lc];
        #pragma unroll
        for (int p = 0; p < 4; p++) {
            int idx = t * 4 + p * 1024;
            int wr = idx >> 7, wc = idx & 127;
            *(float4*)&Ws[wr][wc] = *(const float4*)&W[(size_t)(k0 + wr) * OUTD + wc];
        }
        __syncthreads();

        #pragma unroll 8
        for (int kk = 0; kk < 32; kk++) {
            float4 wq = *(const float4*)&Ws[kk][tx * 4];
            #pragma unroll
            for (int rr = 0; rr < 8; rr++) {
                float hv = hs[ty * 8 + rr][kk];
                acc[rr][0] += hv * wq.x;
                acc[rr][1] += hv * wq.y;
                acc[rr][2] += hv * wq.z;
                acc[rr][3] += hv * wq.w;
            }
        }
        __syncthreads();
    }

    #pragma unroll
    for (int rr = 0; rr < 8; rr++) {
        const int r = row0 + ty * 8 + rr;
        float4 o;
        o.x = __uint_as_float(f2tf32(acc[rr][0]));
        o.y = __uint_as_float(f2tf32(acc[rr][1]));
        o.z = __uint_as_float(f2tf32(acc[rr][2]));
        o.w = __uint_as_float(f2tf32(acc[rr][3]));
        *(float4*)&g_Wh[(size_t)r * OUTD + tx * 4] = o;

        float s1 = acc[rr][0] * a1v[0] + acc[rr][1] * a1v[1] +
                   acc[rr][2] * a1v[2] + acc[rr][3] * a1v[3];
        float s2 = acc[rr][0] * a2v[0] + acc[rr][1] * a2v[1] +
                   acc[rr][2] * a2v[2] + acc[rr][3] * a2v[3];
        #pragma unroll
        for (int off = 16; off; off >>= 1) {
            s1 += __shfl_xor_sync(0xFFFFFFFFu, s1, off);
            s2 += __shfl_xor_sync(0xFFFFFFFFu, s2, off);
        }
        if (tx == 0) { g_f1[r] = s1; g_f2[r] = s2; }
    }
}

// ---------------------------------------------------------------------------
// Kernel 2: fused masked-softmax attention aggregate, tf32 tensor cores,
// cp.async double-buffered Wh tiles, single-buffered weight tile, 2 syncs/iter.
//
// per iter t (buf idx = t&1):
//   wait cp.async; sync#1          (WhS[idx], fjs[idx] ready; MMA(t-1) done)
//   weights(t) -> wts (LDG adj, exp, STS)
//   sync#2
//   issue cp.async for tile t+1 -> WhS[idx^1], fjs[idx^1]   (overlaps MMA)
//   MMA(t): acc += wts(64x64) @ WhS[idx](64x128)
// ---------------------------------------------------------------------------
#define WHS_STRIDE 136
#define WTS_STRIDE 68
#define SM_WHS  0                          // [2][64][136]
#define SM_WTS  (2 * 64 * WHS_STRIDE)      // [64][68]
#define SM_FJS  (SM_WTS + 64 * WTS_STRIDE) // [2][64]
#define SM_ZS   (SM_FJS + 128)             // [64]
#define SM_TOT  (SM_ZS + 64)
#define SM_BYTES (SM_TOT * 4)

__device__ __forceinline__ void mma_tf32(float* d, const uint32_t* a,
                                         uint32_t b0, uint32_t b1) {
    asm volatile(
        "mma.sync.aligned.m16n8k8.row.col.f32.tf32.tf32.f32 "
        "{%0,%1,%2,%3}, {%4,%5,%6,%7}, {%8,%9}, {%0,%1,%2,%3};\n"
        : "+f"(d[0]), "+f"(d[1]), "+f"(d[2]), "+f"(d[3])
        : "r"(a[0]), "r"(a[1]), "r"(a[2]), "r"(a[3]), "r"(b0), "r"(b1));
}

__global__ __launch_bounds__(256, 2) void k2_attn(
    const float* __restrict__ adj, float* __restrict__ out)
{
    extern __shared__ float sm[];
    float* WhS = sm + SM_WHS;    // [2][64][136] tf32 bits (from k1)
    float* wts = sm + SM_WTS;    // [64][68] tf32 bits
    float* fjs = sm + SM_FJS;    // [2][64]
    float* Zs  = sm + SM_ZS;     // [64]
    const uint32_t* Whsu = (const uint32_t*)WhS;
    const uint32_t* wtsu = (const uint32_t*)wts;

    const int t    = threadIdx.x;
    const int wid  = t >> 5;
    const int lane = t & 31;
    const int gid  = lane >> 2;
    const int tig  = lane & 3;
    const int b    = blockIdx.y;
    const int i0   = blockIdx.x * 64;

    const int m_warp = (wid & 3) * 16;
    const int n_warp = (wid >> 2) * 64;

    const int wr  = t >> 2;          // weight row 0..63
    const int wc0 = (t & 3) * 16;    // weight col base

    if (t < 64) Zs[t] = 0.f;

    const float fi_w = g_f1[(size_t)b * NN + i0 + wr];
    const float* Whb = g_Wh + (size_t)b * NN * OUTD;
    const float* f2b = g_f2 + (size_t)b * NN;

    // ---- prologue: async-fill buffer 0 with tile 0
    {
        #pragma unroll
        for (int p = 0; p < 8; p++) {
            int c = t + p * 256;              // 0..2047
            int r = c >> 5, c16 = c & 31;
            cp_async16(&WhS[r * WHS_STRIDE + c16 * 4],
                       &Whb[(size_t)r * OUTD + c16 * 4]);
        }
        if (t < 16) cp_async16(&fjs[t * 4], &f2b[t * 4]);
        CP_COMMIT();
    }

    float acc[8][4];
    #pragma unroll
    for (int i = 0; i < 8; i++)
        #pragma unroll
        for (int j = 0; j < 4; j++) acc[i][j] = 0.f;

    float Zpart = 0.f;

    for (int tt = 0; tt < NN / 64; tt++) {
        const int idx = tt & 1;
        const int j0 = tt * 64;
        const float* WhBuf  = WhS + idx * 64 * WHS_STRIDE;
        const uint32_t* WhBufu = (const uint32_t*)WhBuf;
        const float* fjBuf  = fjs + idx * 64;

        CP_WAIT0();
        __syncthreads();          // sync#1: buffers ready, MMA(t-1) done

        // ---- weight tile: 16 entries/thread, rna-tf32, Z on rounded vals
        {
            const float* adjrow = adj + (size_t)(i0 + wr) * NN + j0 + wc0;
            #pragma unroll
            for (int q = 0; q < 4; q++) {
                float4 av = *(const float4*)&adjrow[q * 4];
                float am[4] = {av.x, av.y, av.z, av.w};
                uint32_t wb[4];
                #pragma unroll
                for (int s = 0; s < 4; s++) {
                    int jj = wc0 + q * 4 + s;
                    float e = fi_w + fjBuf[jj];
                    e = (e >= 0.f) ? e : NEG_SLOPE * e;
                    float w = (am[s] > 0.f) ? __expf(e) : 0.f;
                    uint32_t wt = f2tf32(w);
                    wb[s] = wt;
                    Zpart += __uint_as_float(wt);
                }
                *(uint4*)&wts[wr * WTS_STRIDE + wc0 + q * 4] =
                    make_uint4(wb[0], wb[1], wb[2], wb[3]);
            }
        }
        __syncthreads();          // sync#2: wts complete

        // ---- prefetch next tile (overlaps MMA below)
        if (tt + 1 < NN / 64) {
            const int j1 = j0 + 64;
            float* whdst = WhS + (idx ^ 1) * 64 * WHS_STRIDE;
            #pragma unroll
            for (int p = 0; p < 8; p++) {
                int c = t + p * 256;
                int r = c >> 5, c16 = c & 31;
                cp_async16(&whdst[r * WHS_STRIDE + c16 * 4],
                           &Whb[(size_t)(j1 + r) * OUTD + c16 * 4]);
            }
            if (t < 16)
                cp_async16(&fjs[(idx ^ 1) * 64 + t * 4], &f2b[j1 + t * 4]);
            CP_COMMIT();
        }

        // ---- tensor-core accumulate: acc += wts(64x64) @ WhBuf(64x128)
        #pragma unroll
        for (int k0 = 0; k0 < 64; k0 += 8) {
            uint32_t afrag[4];
            {
                int base = (m_warp + gid) * WTS_STRIDE + k0 + tig;
                afrag[0] = wtsu[base];
                afrag[1] = wtsu[base + 8 * WTS_STRIDE];
                afrag[2] = wtsu[base + 4];
                afrag[3] = wtsu[base + 8 * WTS_STRIDE + 4];
            }
            #pragma unroll
            for (int nt = 0; nt < 8; nt++) {
                int nb = n_warp + nt * 8 + gid;
                uint32_t b0 = WhBufu[(k0 + tig) * WHS_STRIDE + nb];
                uint32_t b1 = WhBufu[(k0 + tig + 4) * WHS_STRIDE + nb];
                mma_tf32(acc[nt], afrag, b0, b1);
            }
        }
    }

    atomicAdd(&Zs[wr], Zpart);
    __syncthreads();

    // ---- epilogue: divide by Z, store
    {
        const int row0e = m_warp + gid;
        const int row1e = row0e + 8;
        const float inv0 = 1.f / Zs[row0e];
        const float inv1 = 1.f / Zs[row1e];
        float* out0 = out + ((size_t)b * NN + i0 + row0e) * OUTD;
        float* out1 = out + ((size_t)b * NN + i0 + row1e) * OUTD;
        #pragma unroll
        for (int nt = 0; nt < 8; nt++) {
            int col = n_warp + nt * 8 + tig * 2;
            *(float2*)&out0[col] = make_float2(acc[nt][0] * inv0,
                                               acc[nt][1] * inv0);
            *(float2*)&out1[col] = make_float2(acc[nt][2] * inv1,
                                               acc[nt][3] * inv1);
        }
    }
}

// ---------------------------------------------------------------------------
extern "C" void kernel_launch(void* const* d_in, const int* in_sizes, int n_in,
                              void* d_out, int out_size)
{
    const float* h   = (const float*)d_in[0];   // (8, 2048, 256)
    const float* adj = (const float*)d_in[1];   // (2048, 2048)
    const float* W   = (const float*)d_in[2];   // (256, 128)
    const float* a   = (const float*)d_in[3];   // (256,)
    float* out = (float*)d_out;                 // (8, 2048, 128)

    k1_gemm_wh<<<ROWS / 64, 256>>>(h, W, a);

    cudaFuncSetAttribute(k2_attn, cudaFuncAttributeMaxDynamicSharedMemorySize,
                         SM_BYTES);
    k2_attn<<<dim3(NN / 64, BB), 256, SM_BYTES>>>(adj, out);
}

// round 6
// speedup vs baseline: 2.2509x; 1.0819x over previous
#include <cuda_runtime.h>
#include <cstdint>

#define BB 8
#define NN 2048
#define IND 256
#define OUTD 128
#define ROWS (BB * NN)   // 16384
#define NEG_SLOPE 0.2f

// Scratch (device globals — no allocation allowed)
__device__ float g_Wh[ROWS * OUTD];   // 8 MB, tf32-rounded values
__device__ float g_E1[ROWS];          // exp(f1)
__device__ float g_G1[ROWS];          // exp(0.2*f1)
__device__ float g_E2[ROWS];          // exp(f2)
__device__ float g_G2[ROWS];          // exp(0.2*f2)

__device__ __forceinline__ uint32_t f2tf32(float x) {
    uint32_t r;
    asm("cvt.rna.tf32.f32 %0, %1;" : "=r"(r) : "f"(x));
    return r;
}

__device__ __forceinline__ void cp_async16(void* dst_smem, const void* src) {
    uint32_t d = (uint32_t)__cvta_generic_to_shared(dst_smem);
    asm volatile("cp.async.cg.shared.global [%0], [%1], 16;\n"
                 :: "r"(d), "l"(src));
}
#define CP_COMMIT() asm volatile("cp.async.commit_group;\n" ::: "memory")
#define CP_WAIT0()  asm volatile("cp.async.wait_group 0;\n" ::: "memory")

// ---------------------------------------------------------------------------
// Kernel 1: Wh = h @ W  (16384x256 @ 256x128).
// Epilogue: f1 = Wh·a1, f2 = Wh·a2 in full precision, then store the FOUR
// exponential factors (exp(f), exp(0.2 f)) so k2's inner loop needs NO exp:
//   exp(leaky(fi+fj)) == max(E1[i]*E2[j], G1[i]*G2[j])
// (for x>=0: e^x >= e^{0.2x}; for x<0: e^{0.2x} > e^x — max picks right branch,
//  and the function is continuous at x=0 so boundary rounding is harmless).
// Wh is stored tf32-rounded (rna) so k2's B operand needs no conversion.
// ---------------------------------------------------------------------------
__global__ __launch_bounds__(256) void k1_gemm_wh(
    const float* __restrict__ h, const float* __restrict__ W,
    const float* __restrict__ a)
{
    __shared__ float hs[64][32];
    __shared__ float Ws[32][128];

    const int t  = threadIdx.x;
    const int ty = t >> 5;
    const int tx = t & 31;
    const int row0 = blockIdx.x * 64;

    float acc[8][4];
    #pragma unroll
    for (int i = 0; i < 8; i++)
        #pragma unroll
        for (int j = 0; j < 4; j++) acc[i][j] = 0.f;

    float a1v[4], a2v[4];
    #pragma unroll
    for (int cc = 0; cc < 4; cc++) {
        a1v[cc] = a[tx * 4 + cc];
        a2v[cc] = a[OUTD + tx * 4 + cc];
    }

    const int lr = t >> 3;
    const int lc = (t & 7) * 4;

    for (int k0 = 0; k0 < IND; k0 += 32) {
        *(float4*)&hs[lr][lc] =
            *(const float4*)&h[(size_t)(row0 + lr) * IND + k0 + lc];
        *(float4*)&hs[lr + 32][lc] =
            *(const float4*)&h[(size_t)(row0 + lr + 32) * IND + k0 + lc];
        #pragma unroll
        for (int p = 0; p < 4; p++) {
            int idx = t * 4 + p * 1024;
            int wr = idx >> 7, wc = idx & 127;
            *(float4*)&Ws[wr][wc] = *(const float4*)&W[(size_t)(k0 + wr) * OUTD + wc];
        }
        __syncthreads();

        #pragma unroll 8
        for (int kk = 0; kk < 32; kk++) {
            float4 wq = *(const float4*)&Ws[kk][tx * 4];
            #pragma unroll
            for (int rr = 0; rr < 8; rr++) {
                float hv = hs[ty * 8 + rr][kk];
                acc[rr][0] += hv * wq.x;
                acc[rr][1] += hv * wq.y;
                acc[rr][2] += hv * wq.z;
                acc[rr][3] += hv * wq.w;
            }
        }
        __syncthreads();
    }

    #pragma unroll
    for (int rr = 0; rr < 8; rr++) {
        const int r = row0 + ty * 8 + rr;
        float4 o;
        o.x = __uint_as_float(f2tf32(acc[rr][0]));
        o.y = __uint_as_float(f2tf32(acc[rr][1]));
        o.z = __uint_as_float(f2tf32(acc[rr][2]));
        o.w = __uint_as_float(f2tf32(acc[rr][3]));
        *(float4*)&g_Wh[(size_t)r * OUTD + tx * 4] = o;

        float s1 = acc[rr][0] * a1v[0] + acc[rr][1] * a1v[1] +
                   acc[rr][2] * a1v[2] + acc[rr][3] * a1v[3];
        float s2 = acc[rr][0] * a2v[0] + acc[rr][1] * a2v[1] +
                   acc[rr][2] * a2v[2] + acc[rr][3] * a2v[3];
        #pragma unroll
        for (int off = 16; off; off >>= 1) {
            s1 += __shfl_xor_sync(0xFFFFFFFFu, s1, off);
            s2 += __shfl_xor_sync(0xFFFFFFFFu, s2, off);
        }
        if (tx == 0) {
            g_E1[r] = expf(s1);
            g_G1[r] = expf(NEG_SLOPE * s1);
            g_E2[r] = expf(s2);
            g_G2[r] = expf(NEG_SLOPE * s2);
        }
    }
}

// ---------------------------------------------------------------------------
// Kernel 2: fused masked-softmax attention aggregate, tf32 mma.sync,
// cp.async double-buffered Wh/E2/G2 tiles, exp-free weight computation,
// m32n32 warp tiles (2 m-warps x 4 n-warps).
//
// per iter t (buf idx = t&1):
//   wait cp.async; sync#1          (buffers ready; MMA(t-1) done)
//   weights(t): w = max(Efi*Efj, Gfi*Gfj) * adj  -> wts (tf32), Z += w
//   sync#2
//   issue cp.async for tile t+1    (overlaps MMA)
//   MMA(t): acc += wts(64x64) @ WhS[idx](64x128)
// ---------------------------------------------------------------------------
#define WHS_STRIDE 136
#define WTS_STRIDE 68
#define SM_WHS  0                          // [2][64][136]
#define SM_WTS  (2 * 64 * WHS_STRIDE)      // [64][68]
#define SM_EJS  (SM_WTS + 64 * WTS_STRIDE) // [2][64]
#define SM_GJS  (SM_EJS + 128)             // [2][64]
#define SM_ZS   (SM_GJS + 128)             // [64]
#define SM_TOT  (SM_ZS + 64)
#define SM_BYTES (SM_TOT * 4)

__device__ __forceinline__ void mma_tf32(float* d, const uint32_t* a,
                                         uint32_t b0, uint32_t b1) {
    asm volatile(
        "mma.sync.aligned.m16n8k8.row.col.f32.tf32.tf32.f32 "
        "{%0,%1,%2,%3}, {%4,%5,%6,%7}, {%8,%9}, {%0,%1,%2,%3};\n"
        : "+f"(d[0]), "+f"(d[1]), "+f"(d[2]), "+f"(d[3])
        : "r"(a[0]), "r"(a[1]), "r"(a[2]), "r"(a[3]), "r"(b0), "r"(b1));
}

__global__ __launch_bounds__(256, 2) void k2_attn(
    const float* __restrict__ adj, float* __restrict__ out)
{
    extern __shared__ float sm[];
    float* WhS = sm + SM_WHS;    // [2][64][136] tf32 bits (from k1)
    float* wts = sm + SM_WTS;    // [64][68] tf32 bits
    float* ejs = sm + SM_EJS;    // [2][64] exp(f2)
    float* gjs = sm + SM_GJS;    // [2][64] exp(0.2 f2)
    float* Zs  = sm + SM_ZS;     // [64]
    const uint32_t* wtsu = (const uint32_t*)wts;

    const int t    = threadIdx.x;
    const int wid  = t >> 5;
    const int lane = t & 31;
    const int gid  = lane >> 2;
    const int tig  = lane & 3;
    const int b    = blockIdx.y;
    const int i0   = blockIdx.x * 64;

    // m32n32 warp tiles: 2 warps on M (32 rows each), 4 on N (32 cols each)
    const int m_warp = (wid & 1) * 32;
    const int n_warp = (wid >> 1) * 32;

    const int wr  = t >> 2;          // weight row 0..63
    const int wc0 = (t & 3) * 16;    // weight col base

    if (t < 64) Zs[t] = 0.f;

    const float Efi = g_E1[(size_t)b * NN + i0 + wr];
    const float Gfi = g_G1[(size_t)b * NN + i0 + wr];
    const float* Whb = g_Wh + (size_t)b * NN * OUTD;
    const float* E2b = g_E2 + (size_t)b * NN;
    const float* G2b = g_G2 + (size_t)b * NN;

    // ---- prologue: async-fill buffer 0 with tile 0
    {
        #pragma unroll
        for (int p = 0; p < 8; p++) {
            int c = t + p * 256;              // 0..2047
            int r = c >> 5, c16 = c & 31;
            cp_async16(&WhS[r * WHS_STRIDE + c16 * 4],
                       &Whb[(size_t)r * OUTD + c16 * 4]);
        }
        if (t < 16)      cp_async16(&ejs[t * 4],        &E2b[t * 4]);
        else if (t < 32) cp_async16(&gjs[(t - 16) * 4], &G2b[(t - 16) * 4]);
        CP_COMMIT();
    }

    float acc[2][4][4];
    #pragma unroll
    for (int u = 0; u < 2; u++)
        #pragma unroll
        for (int v = 0; v < 4; v++)
            #pragma unroll
            for (int j = 0; j < 4; j++) acc[u][v][j] = 0.f;

    float Zpart = 0.f;

    for (int tt = 0; tt < NN / 64; tt++) {
        const int idx = tt & 1;
        const int j0 = tt * 64;
        const uint32_t* WhBufu =
            (const uint32_t*)(WhS + idx * 64 * WHS_STRIDE);
        const float* ejBuf = ejs + idx * 64;
        const float* gjBuf = gjs + idx * 64;

        CP_WAIT0();
        __syncthreads();          // sync#1: buffers ready, MMA(t-1) done

        // ---- weight tile: 16 entries/thread, NO exp, branchless
        {
            const float* adjrow = adj + (size_t)(i0 + wr) * NN + j0 + wc0;
            #pragma unroll
            for (int q = 0; q < 4; q++) {
                float4 av = *(const float4*)&adjrow[q * 4];
                float4 ej = *(const float4*)&ejBuf[wc0 + q * 4];
                float4 gj = *(const float4*)&gjBuf[wc0 + q * 4];
                float am[4] = {av.x, av.y, av.z, av.w};
                float ev[4] = {ej.x, ej.y, ej.z, ej.w};
                float gv[4] = {gj.x, gj.y, gj.z, gj.w};
                uint32_t wb[4];
                #pragma unroll
                for (int s = 0; s < 4; s++) {
                    float w = fmaxf(Efi * ev[s], Gfi * gv[s]) * am[s];
                    uint32_t wt = f2tf32(w);
                    wb[s] = wt;
                    Zpart += __uint_as_float(wt);
                }
                *(uint4*)&wts[wr * WTS_STRIDE + wc0 + q * 4] =
                    make_uint4(wb[0], wb[1], wb[2], wb[3]);
            }
        }
        __syncthreads();          // sync#2: wts complete

        // ---- prefetch next tile (overlaps MMA below)
        if (tt + 1 < NN / 64) {
            const int j1 = j0 + 64;
            float* whdst = WhS + (idx ^ 1) * 64 * WHS_STRIDE;
            #pragma unroll
            for (int p = 0; p < 8; p++) {
                int c = t + p * 256;
                int r = c >> 5, c16 = c & 31;
                cp_async16(&whdst[r * WHS_STRIDE + c16 * 4],
                           &Whb[(size_t)(j1 + r) * OUTD + c16 * 4]);
            }
            if (t < 16)
                cp_async16(&ejs[(idx ^ 1) * 64 + t * 4], &E2b[j1 + t * 4]);
            else if (t < 32)
                cp_async16(&gjs[(idx ^ 1) * 64 + (t - 16) * 4],
                           &G2b[j1 + (t - 16) * 4]);
            CP_COMMIT();
        }

        // ---- tensor-core accumulate: acc += wts(64x64) @ WhBuf(64x128)
        #pragma unroll
        for (int k0 = 0; k0 < 64; k0 += 8) {
            uint32_t afrag[2][4];
            #pragma unroll
            for (int u = 0; u < 2; u++) {
                int base = (m_warp + u * 16 + gid) * WTS_STRIDE + k0 + tig;
                afrag[u][0] = wtsu[base];
                afrag[u][1] = wtsu[base + 8 * WTS_STRIDE];
                afrag[u][2] = wtsu[base + 4];
                afrag[u][3] = wtsu[base + 8 * WTS_STRIDE + 4];
            }
            #pragma unroll
            for (int v = 0; v < 4; v++) {
                int nb = n_warp + v * 8 + gid;
                uint32_t b0 = WhBufu[(k0 + tig) * WHS_STRIDE + nb];
                uint32_t b1 = WhBufu[(k0 + tig + 4) * WHS_STRIDE + nb];
                mma_tf32(acc[0][v], afrag[0], b0, b1);
                mma_tf32(acc[1][v], afrag[1], b0, b1);
            }
        }
    }

    atomicAdd(&Zs[wr], Zpart);
    __syncthreads();

    // ---- epilogue: divide by Z, store
    #pragma unroll
    for (int u = 0; u < 2; u++) {
        const int row0e = m_warp + u * 16 + gid;
        const int row1e = row0e + 8;
        const float inv0 = 1.f / Zs[row0e];
        const float inv1 = 1.f / Zs[row1e];
        float* out0 = out + ((size_t)b * NN + i0 + row0e) * OUTD;
        float* out1 = out + ((size_t)b * NN + i0 + row1e) * OUTD;
        #pragma unroll
        for (int v = 0; v < 4; v++) {
            int col = n_warp + v * 8 + tig * 2;
            *(float2*)&out0[col] = make_float2(acc[u][v][0] * inv0,
                                               acc[u][v][1] * inv0);
            *(float2*)&out1[col] = make_float2(acc[u][v][2] * inv1,
                                               acc[u][v][3] * inv1);
        }
    }
}

// ---------------------------------------------------------------------------
extern "C" void kernel_launch(void* const* d_in, const int* in_sizes, int n_in,
                              void* d_out, int out_size)
{
    const float* h   = (const float*)d_in[0];   // (8, 2048, 256)
    const float* adj = (const float*)d_in[1];   // (2048, 2048)
    const float* W   = (const float*)d_in[2];   // (256, 128)
    const float* a   = (const float*)d_in[3];   // (256,)
    float* out = (float*)d_out;                 // (8, 2048, 128)

    k1_gemm_wh<<<ROWS / 64, 256>>>(h, W, a);

    cudaFuncSetAttribute(k2_attn, cudaFuncAttributeMaxDynamicSharedMemorySize,
                         SM_BYTES);
    k2_attn<<<dim3(NN / 64, BB), 256, SM_BYTES>>>(adj, out);
}